// round 4
// baseline (speedup 1.0000x reference)
#include <cuda_runtime.h>
#include <cuda_fp16.h>
#include <cuda_bf16.h>
#include <cstdint>

#define DINLINE __device__ __forceinline__

// ---------------- problem constants ----------------
static constexpr int M_TOTAL = 16384;   // 8 * 2048
static constexpr int N_TOTAL = 4096;    // out features
static constexpr int K_TOTAL = 4096;    // in features
static constexpr int NUM_GROUPS = 524288;

// ---------------- GEMM tiling ----------------
static constexpr int BM = 128;
static constexpr int BN = 256;
static constexpr int BK = 32;                    // halves per k-tile
static constexpr int KTILES = K_TOTAL / BK;      // 128
static constexpr int STAGES = 4;
static constexpr int MT = M_TOTAL / BM;          // 128
static constexpr int NT = N_TOTAL / BN;          // 16
static constexpr int GROUP_M = 16;               // L2 grid swizzle

// smem: rows padded to 40 halves (80 bytes) -> conflict-free ldmatrix phases
// (16B segment index mod 8 = {0,5,2,7,4,1,6,3} over 8 consecutive rows)
static constexpr int ROW_BYTES    = 80;
static constexpr int A_TILE_BYTES = BM * ROW_BYTES;           // 10240
static constexpr int B_TILE_BYTES = BN * ROW_BYTES;           // 20480
static constexpr int STAGE_BYTES  = A_TILE_BYTES + B_TILE_BYTES; // 30720
static constexpr int SMEM_TOTAL   = STAGES * STAGE_BYTES;     // 122880

// scratch (device globals: allocation-free scratch per harness rules)
__device__ __align__(128) __half g_W[(size_t)N_TOTAL * K_TOTAL];  // 32 MB
__device__ __align__(128) __half g_X[(size_t)M_TOTAL * K_TOTAL];  // 128 MB
__device__ __align__(128) float  g_bias[N_TOTAL];
__device__ int g_dtype_flag;   // 0 = fp32, 1 = fp16, 2 = bf16

// ---------------- PTX helpers (compute_103-safe) ----------------
DINLINE uint32_t smem_u32(const void* p) {
    uint32_t a;
    asm("{ .reg .u64 t; cvta.to.shared.u64 t, %1; cvt.u32.u64 %0, t; }" : "=r"(a) : "l"(p));
    return a;
}

DINLINE void cp_async16(uint32_t s, const void* g) {
    asm volatile("cp.async.cg.shared.global [%0], [%1], 16;" :: "r"(s), "l"(g) : "memory");
}
DINLINE void cp_commit() { asm volatile("cp.async.commit_group;" ::: "memory"); }
DINLINE void cp_wait2()  { asm volatile("cp.async.wait_group 2;"  ::: "memory"); }

DINLINE void ldsm_x4(uint32_t* r, uint32_t addr) {
    asm volatile("ldmatrix.sync.aligned.m8n8.x4.shared.b16 {%0,%1,%2,%3}, [%4];"
                 : "=r"(r[0]), "=r"(r[1]), "=r"(r[2]), "=r"(r[3]) : "r"(addr));
}

DINLINE void mma_16816(float* d, const uint32_t* a, const uint32_t* b) {
    asm volatile("mma.sync.aligned.m16n8k16.row.col.f32.f16.f16.f32 "
                 "{%0,%1,%2,%3}, {%4,%5,%6,%7}, {%8,%9}, {%0,%1,%2,%3};"
                 : "+f"(d[0]), "+f"(d[1]), "+f"(d[2]), "+f"(d[3])
                 : "r"(a[0]), "r"(a[1]), "r"(a[2]), "r"(a[3]), "r"(b[0]), "r"(b[1]));
}

// ---------------- dtype detection ----------------
// scales are uniform in [0.01, 1.0). Disambiguate fp32 / fp16 / bf16 by range.
__global__ void detect_kernel(const uint32_t* __restrict__ sc_raw) {
    uint32_t w0 = sc_raw[0], w1 = sc_raw[1], w2 = sc_raw[2], w3 = sc_raw[3];
    float f[4] = {__uint_as_float(w0), __uint_as_float(w1),
                  __uint_as_float(w2), __uint_as_float(w3)};
    bool f32ok = true;
    #pragma unroll
    for (int i = 0; i < 4; i++)
        f32ok = f32ok && isfinite(f[i]) && f[i] >= 0.004f && f[i] <= 1.1f;

    bool f16ok = true;
    uint32_t ws[4] = {w0, w1, w2, w3};
    #pragma unroll
    for (int i = 0; i < 4; i++) {
        __half lo = __ushort_as_half((unsigned short)(ws[i] & 0xFFFF));
        __half hi = __ushort_as_half((unsigned short)(ws[i] >> 16));
        float a = __half2float(lo), b = __half2float(hi);
        f16ok = f16ok && a >= 0.004f && a <= 1.02f && b >= 0.004f && b <= 1.02f;
    }
    g_dtype_flag = f32ok ? 0 : (f16ok ? 1 : 2);
}

DINLINE float load_scalar(const void* p, int idx, int flag) {
    if (flag == 0) return ((const float*)p)[idx];
    if (flag == 1) return __half2float(((const __half*)p)[idx]);
    return __bfloat162float(((const __nv_bfloat16*)p)[idx]);
}

// ---------------- prepass kernels ----------------
__global__ void __launch_bounds__(256) dequant_kernel(const int* __restrict__ wp,
                                                      const void* __restrict__ sc,
                                                      __half* __restrict__ W) {
    int p = blockIdx.x * blockDim.x + threadIdx.x;   // one packed int32 -> 2 weights
    if (p >= NUM_GROUPS * 16) return;
    int flag = g_dtype_flag;
    int g  = p >> 4;
    int wi = p & 15;
    int v  = __ldg(wp + p);
    float s  = load_scalar(sc, g, flag);
    float w0 = ((float)(v & 7)        * (2.0f / 7.0f) - 1.0f) * s;
    float w1 = ((float)((v >> 3) & 7) * (2.0f / 7.0f) - 1.0f) * s;
    int row = g >> 7;                       // 128 groups per out-row
    int col = ((g & 127) << 5) | (wi << 1);
    *reinterpret_cast<__half2*>(W + (size_t)row * K_TOTAL + col) = __floats2half2_rn(w0, w1);
}

__global__ void __launch_bounds__(256) bias_cvt_kernel(const void* __restrict__ bias) {
    int i = blockIdx.x * blockDim.x + threadIdx.x;
    if (i >= N_TOTAL) return;
    g_bias[i] = load_scalar(bias, i, g_dtype_flag);
}

__global__ void __launch_bounds__(256) cvt_kernel(const float4* __restrict__ x,
                                                  __half2* __restrict__ xh) {
    int i = blockIdx.x * blockDim.x + threadIdx.x;
    if (i >= (M_TOTAL * K_TOTAL) / 4) return;
    float4 v = x[i];
    xh[2 * i + 0] = __floats2half2_rn(v.x, v.y);
    xh[2 * i + 1] = __floats2half2_rn(v.z, v.w);
}

// ---------------- GEMM kernel (HMMA mma.sync, warp tile 64x64) -------------
__global__ void __launch_bounds__(256, 1) gemm_kernel(
    const __half* __restrict__ X,      // [M, K] fp16
    const __half* __restrict__ W,      // [N, K] fp16
    float* __restrict__ out)           // [M, N]
{
    extern __shared__ __align__(128) char smem[];
    const uint32_t sb = smem_u32(smem);

    const int tid = threadIdx.x;
    const int wid = tid >> 5, lid = tid & 31;
    const int warp_m = wid & 1;        // 2 warps along M (64 rows each)
    const int warp_n = wid >> 1;       // 4 warps along N (64 cols each)

    // L2-friendly grid swizzle: mtile fastest within GROUP_M x NT supergroups
    const int bid    = blockIdx.x;
    const int within = bid & (GROUP_M * NT - 1);       // 256-1
    const int mtile  = (bid >> 8) * GROUP_M + (within & (GROUP_M - 1));
    const int ntile  = within >> 4;                    // /GROUP_M

    const __half* gA = X + (size_t)mtile * BM * K_TOTAL;
    const __half* gB = W + (size_t)ntile * BN * K_TOTAL;

    // loader: A = 512 chunks (2/thread), B = 1024 chunks (4/thread); chunk=16B
    auto load_stage = [&](int s, int kt) {
        const uint32_t abase = sb + s * STAGE_BYTES;
        const uint32_t bbase = abase + A_TILE_BYTES;
        #pragma unroll
        for (int i = 0; i < 2; i++) {
            int c = tid + i * 256;
            int row = c >> 2, cc = c & 3;
            cp_async16(abase + row * ROW_BYTES + cc * 16,
                       gA + (size_t)row * K_TOTAL + kt * BK + cc * 8);
        }
        #pragma unroll
        for (int i = 0; i < 4; i++) {
            int c = tid + i * 256;
            int row = c >> 2, cc = c & 3;
            cp_async16(bbase + row * ROW_BYTES + cc * 16,
                       gB + (size_t)row * K_TOTAL + kt * BK + cc * 8);
        }
    };

    #pragma unroll
    for (int s = 0; s < STAGES - 1; s++) { load_stage(s, s); cp_commit(); }

    float acc[4][8][4];
    #pragma unroll
    for (int mt = 0; mt < 4; mt++)
        #pragma unroll
        for (int nt = 0; nt < 8; nt++)
            #pragma unroll
            for (int i = 0; i < 4; i++) acc[mt][nt][i] = 0.0f;

    const int a_row = warp_m * 64 + (lid & 15);          // + mt*16
    const int a_chk = lid >> 4;                          // + ks*2
    const int b_row = warp_n * 64 + (lid & 7) + ((lid >> 4) << 3);  // + np*16
    const int b_chk = (lid >> 3) & 1;                    // + ks*2

    #pragma unroll 1
    for (int kt = 0; kt < KTILES; kt++) {
        cp_wait2();
        __syncthreads();
        if (kt + STAGES - 1 < KTILES) load_stage((kt + STAGES - 1) & (STAGES - 1), kt + STAGES - 1);
        cp_commit();

        const int s = kt & (STAGES - 1);
        const uint32_t abase = sb + s * STAGE_BYTES;
        const uint32_t bbase = abase + A_TILE_BYTES;

        #pragma unroll
        for (int ks = 0; ks < 2; ks++) {
            uint32_t af[4][4];
            #pragma unroll
            for (int mt = 0; mt < 4; mt++)
                ldsm_x4(af[mt], abase + (a_row + mt * 16) * ROW_BYTES + (a_chk + ks * 2) * 16);

            uint32_t bf[8][2];
            #pragma unroll
            for (int np = 0; np < 4; np++) {
                uint32_t r[4];
                ldsm_x4(r, bbase + (b_row + np * 16) * ROW_BYTES + (b_chk + ks * 2) * 16);
                bf[2 * np][0] = r[0]; bf[2 * np][1] = r[1];
                bf[2 * np + 1][0] = r[2]; bf[2 * np + 1][1] = r[3];
            }

            #pragma unroll
            for (int mt = 0; mt < 4; mt++)
                #pragma unroll
                for (int nt = 0; nt < 8; nt++)
                    mma_16816(acc[mt][nt], af[mt], bf[nt]);
        }
    }

    // ---- epilogue: acc + bias -> out (fp32) ----
    const int orow0 = mtile * BM + warp_m * 64 + (lid >> 2);
    const int ocol0 = ntile * BN + warp_n * 64 + (lid & 3) * 2;

    #pragma unroll
    for (int nt = 0; nt < 8; nt++) {
        float2 bv = *reinterpret_cast<const float2*>(&g_bias[ocol0 + nt * 8]);
        #pragma unroll
        for (int mt = 0; mt < 4; mt++) {
            int r0 = orow0 + mt * 16;
            float* p0 = out + (size_t)r0 * N_TOTAL + ocol0 + nt * 8;
            float* p1 = out + (size_t)(r0 + 8) * N_TOTAL + ocol0 + nt * 8;
            *reinterpret_cast<float2*>(p0) = make_float2(acc[mt][nt][0] + bv.x, acc[mt][nt][1] + bv.y);
            *reinterpret_cast<float2*>(p1) = make_float2(acc[mt][nt][2] + bv.x, acc[mt][nt][3] + bv.y);
        }
    }
}

// ---------------- host launcher ----------------
extern "C" void kernel_launch(void* const* d_in, const int* in_sizes, int n_in,
                              void* d_out, int out_size) {
    const float* x      = (const float*)d_in[0];
    const int*   wp     = (const int*)d_in[1];
    const void*  scales = d_in[2];
    const void*  bias   = d_in[3];
    float*       out    = (float*)d_out;

    void* wptr = nullptr; cudaGetSymbolAddress(&wptr, g_W);
    void* xptr = nullptr; cudaGetSymbolAddress(&xptr, g_X);

    detect_kernel<<<1, 1>>>((const uint32_t*)scales);
    dequant_kernel<<<(NUM_GROUPS * 16 + 255) / 256, 256>>>(wp, scales, (__half*)wptr);
    bias_cvt_kernel<<<(N_TOTAL + 255) / 256, 256>>>(bias);
    cvt_kernel<<<((M_TOTAL * K_TOTAL) / 4 + 255) / 256, 256>>>((const float4*)x, (__half2*)xptr);

    cudaFuncSetAttribute(gemm_kernel, cudaFuncAttributeMaxDynamicSharedMemorySize, SMEM_TOTAL);
    gemm_kernel<<<MT * NT, 256, SMEM_TOTAL>>>((const __half*)xptr, (const __half*)wptr, out);
}

// round 5
// speedup vs baseline: 1.2869x; 1.2869x over previous
#include <cuda_runtime.h>
#include <cuda_fp16.h>
#include <cuda_bf16.h>
#include <cstdint>

#define DINLINE __device__ __forceinline__

// ---------------- problem constants ----------------
static constexpr int M_TOTAL = 16384;   // 8 * 2048
static constexpr int N_TOTAL = 4096;    // out features
static constexpr int K_TOTAL = 4096;    // in features
static constexpr int NUM_GROUPS = 524288;

// ---------------- GEMM tiling ----------------
static constexpr int BM = 128;
static constexpr int BN = 128;
static constexpr int BK = 64;                    // halves per k-tile
static constexpr int KTILES = K_TOTAL / BK;      // 64
static constexpr int STAGES = 3;
static constexpr int MT = M_TOTAL / BM;          // 128
static constexpr int NT = N_TOTAL / BN;          // 32
static constexpr int GROUP_M = 16;               // L2 grid swizzle

// smem: rows padded to 144 bytes (128 data + 16 pad).
// 144 mod 128 = 16 -> 8 consecutive rows hit 8 distinct 16B segments
// within a 128B bank phase => conflict-free ldmatrix.
static constexpr int ROW_BYTES    = 144;
static constexpr int A_TILE_BYTES = BM * ROW_BYTES;              // 18432
static constexpr int B_TILE_BYTES = BN * ROW_BYTES;              // 18432
static constexpr int STAGE_BYTES  = A_TILE_BYTES + B_TILE_BYTES; // 36864
static constexpr int SMEM_TOTAL   = STAGES * STAGE_BYTES;        // 110592 (x2 CTAs = 221KB)

// scratch (device globals: allocation-free scratch per harness rules)
__device__ __align__(128) __half g_W[(size_t)N_TOTAL * K_TOTAL];  // 32 MB
__device__ __align__(128) __half g_X[(size_t)M_TOTAL * K_TOTAL];  // 128 MB
__device__ __align__(128) float  g_bias[N_TOTAL];
__device__ int g_dtype_flag;   // 0 = fp32, 1 = fp16, 2 = bf16

// ---------------- PTX helpers (compute_103-safe) ----------------
DINLINE uint32_t smem_u32(const void* p) {
    uint32_t a;
    asm("{ .reg .u64 t; cvta.to.shared.u64 t, %1; cvt.u32.u64 %0, t; }" : "=r"(a) : "l"(p));
    return a;
}

DINLINE void cp_async16(uint32_t s, const void* g) {
    asm volatile("cp.async.cg.shared.global [%0], [%1], 16;" :: "r"(s), "l"(g) : "memory");
}
DINLINE void cp_commit() { asm volatile("cp.async.commit_group;" ::: "memory"); }
DINLINE void cp_wait1()  { asm volatile("cp.async.wait_group 1;"  ::: "memory"); }

DINLINE void ldsm_x4(uint32_t* r, uint32_t addr) {
    asm volatile("ldmatrix.sync.aligned.m8n8.x4.shared.b16 {%0,%1,%2,%3}, [%4];"
                 : "=r"(r[0]), "=r"(r[1]), "=r"(r[2]), "=r"(r[3]) : "r"(addr));
}

DINLINE void mma_16816(float* d, const uint32_t* a, const uint32_t* b) {
    asm volatile("mma.sync.aligned.m16n8k16.row.col.f32.f16.f16.f32 "
                 "{%0,%1,%2,%3}, {%4,%5,%6,%7}, {%8,%9}, {%0,%1,%2,%3};"
                 : "+f"(d[0]), "+f"(d[1]), "+f"(d[2]), "+f"(d[3])
                 : "r"(a[0]), "r"(a[1]), "r"(a[2]), "r"(a[3]), "r"(b[0]), "r"(b[1]));
}

// ---------------- dtype detection ----------------
// scales are uniform in [0.01, 1.0). Disambiguate fp32 / fp16 / bf16 by range.
__global__ void detect_kernel(const uint32_t* __restrict__ sc_raw) {
    uint32_t w0 = sc_raw[0], w1 = sc_raw[1], w2 = sc_raw[2], w3 = sc_raw[3];
    float f[4] = {__uint_as_float(w0), __uint_as_float(w1),
                  __uint_as_float(w2), __uint_as_float(w3)};
    bool f32ok = true;
    #pragma unroll
    for (int i = 0; i < 4; i++)
        f32ok = f32ok && isfinite(f[i]) && f[i] >= 0.004f && f[i] <= 1.1f;

    bool f16ok = true;
    uint32_t ws[4] = {w0, w1, w2, w3};
    #pragma unroll
    for (int i = 0; i < 4; i++) {
        __half lo = __ushort_as_half((unsigned short)(ws[i] & 0xFFFF));
        __half hi = __ushort_as_half((unsigned short)(ws[i] >> 16));
        float a = __half2float(lo), b = __half2float(hi);
        f16ok = f16ok && a >= 0.004f && a <= 1.02f && b >= 0.004f && b <= 1.02f;
    }
    g_dtype_flag = f32ok ? 0 : (f16ok ? 1 : 2);
}

DINLINE float load_scalar(const void* p, int idx, int flag) {
    if (flag == 0) return ((const float*)p)[idx];
    if (flag == 1) return __half2float(((const __half*)p)[idx]);
    return __bfloat162float(((const __nv_bfloat16*)p)[idx]);
}

// ---------------- prepass kernels ----------------
__global__ void __launch_bounds__(256) dequant_kernel(const int* __restrict__ wp,
                                                      const void* __restrict__ sc,
                                                      __half* __restrict__ W) {
    int p = blockIdx.x * blockDim.x + threadIdx.x;   // one packed int32 -> 2 weights
    if (p >= NUM_GROUPS * 16) return;
    int flag = g_dtype_flag;
    int g  = p >> 4;
    int wi = p & 15;
    int v  = __ldg(wp + p);
    float s  = load_scalar(sc, g, flag);
    float w0 = ((float)(v & 7)        * (2.0f / 7.0f) - 1.0f) * s;
    float w1 = ((float)((v >> 3) & 7) * (2.0f / 7.0f) - 1.0f) * s;
    int row = g >> 7;                       // 128 groups per out-row
    int col = ((g & 127) << 5) | (wi << 1);
    *reinterpret_cast<__half2*>(W + (size_t)row * K_TOTAL + col) = __floats2half2_rn(w0, w1);
}

__global__ void __launch_bounds__(256) bias_cvt_kernel(const void* __restrict__ bias) {
    int i = blockIdx.x * blockDim.x + threadIdx.x;
    if (i >= N_TOTAL) return;
    g_bias[i] = load_scalar(bias, i, g_dtype_flag);
}

__global__ void __launch_bounds__(256) cvt_kernel(const float4* __restrict__ x,
                                                  __half2* __restrict__ xh) {
    int i = blockIdx.x * blockDim.x + threadIdx.x;
    if (i >= (M_TOTAL * K_TOTAL) / 4) return;
    float4 v = x[i];
    xh[2 * i + 0] = __floats2half2_rn(v.x, v.y);
    xh[2 * i + 1] = __floats2half2_rn(v.z, v.w);
}

// ---------------- GEMM kernel (HMMA mma.sync, warp tile 32x64, occ 2) ------
__global__ void __launch_bounds__(256, 2) gemm_kernel(
    const __half* __restrict__ X,      // [M, K] fp16
    const __half* __restrict__ W,      // [N, K] fp16
    float* __restrict__ out)           // [M, N]
{
    extern __shared__ __align__(128) char smem[];
    const uint32_t sb = smem_u32(smem);

    const int tid = threadIdx.x;
    const int wid = tid >> 5, lid = tid & 31;
    const int warp_m = wid & 3;        // 4 warps along M (32 rows each)
    const int warp_n = wid >> 2;       // 2 warps along N (64 cols each)

    // L2-friendly grid swizzle: GROUP_M rows of tiles per super-group
    const int bid    = blockIdx.x;
    const int within = bid & (GROUP_M * NT - 1);           // 0..511
    const int mtile  = (bid >> 9) * GROUP_M + (within & (GROUP_M - 1));
    const int ntile  = within >> 4;                        // 0..31

    const __half* gA = X + (size_t)mtile * BM * K_TOTAL;
    const __half* gB = W + (size_t)ntile * BN * K_TOTAL;

    // loader: A = 1024 chunks (4/thread), B = 1024 chunks (4/thread); chunk=16B
    auto load_stage = [&](int s, int kt) {
        const uint32_t abase = sb + s * STAGE_BYTES;
        const uint32_t bbase = abase + A_TILE_BYTES;
        #pragma unroll
        for (int i = 0; i < 4; i++) {
            int c = tid + i * 256;
            int row = c >> 3, cc = c & 7;
            cp_async16(abase + row * ROW_BYTES + cc * 16,
                       gA + (size_t)row * K_TOTAL + kt * BK + cc * 8);
        }
        #pragma unroll
        for (int i = 0; i < 4; i++) {
            int c = tid + i * 256;
            int row = c >> 3, cc = c & 7;
            cp_async16(bbase + row * ROW_BYTES + cc * 16,
                       gB + (size_t)row * K_TOTAL + kt * BK + cc * 8);
        }
    };

    load_stage(0, 0); cp_commit();
    load_stage(1, 1); cp_commit();

    float acc[2][8][4];
    #pragma unroll
    for (int mt = 0; mt < 2; mt++)
        #pragma unroll
        for (int nt = 0; nt < 8; nt++)
            #pragma unroll
            for (int i = 0; i < 4; i++) acc[mt][nt][i] = 0.0f;

    const int a_row = warp_m * 32 + (lid & 15);                     // + mt*16
    const int a_chk = lid >> 4;                                     // + ks*2
    const int b_row = warp_n * 64 + (lid & 7) + ((lid >> 4) << 3);  // + np*16
    const int b_chk = (lid >> 3) & 1;                               // + ks*2

    int s_cur = 0, s_load = 2;
    #pragma unroll 1
    for (int kt = 0; kt < KTILES; kt++) {
        cp_wait1();
        __syncthreads();
        if (kt + 2 < KTILES) load_stage(s_load, kt + 2);
        cp_commit();

        const uint32_t abase = sb + s_cur * STAGE_BYTES;
        const uint32_t bbase = abase + A_TILE_BYTES;

        #pragma unroll
        for (int ks = 0; ks < 4; ks++) {
            uint32_t af[2][4];
            #pragma unroll
            for (int mt = 0; mt < 2; mt++)
                ldsm_x4(af[mt], abase + (a_row + mt * 16) * ROW_BYTES + (a_chk + ks * 2) * 16);

            uint32_t bf[8][2];
            #pragma unroll
            for (int np = 0; np < 4; np++) {
                uint32_t r[4];
                ldsm_x4(r, bbase + (b_row + np * 16) * ROW_BYTES + (b_chk + ks * 2) * 16);
                bf[2 * np][0] = r[0]; bf[2 * np][1] = r[1];
                bf[2 * np + 1][0] = r[2]; bf[2 * np + 1][1] = r[3];
            }

            #pragma unroll
            for (int mt = 0; mt < 2; mt++)
                #pragma unroll
                for (int nt = 0; nt < 8; nt++)
                    mma_16816(acc[mt][nt], af[mt], bf[nt]);
        }

        s_cur  = (s_cur  == STAGES - 1) ? 0 : s_cur + 1;
        s_load = (s_load == STAGES - 1) ? 0 : s_load + 1;
    }

    // ---- epilogue: acc + bias -> out (fp32) ----
    const int orow0 = mtile * BM + warp_m * 32 + (lid >> 2);
    const int ocol0 = ntile * BN + warp_n * 64 + (lid & 3) * 2;

    #pragma unroll
    for (int nt = 0; nt < 8; nt++) {
        float2 bv = *reinterpret_cast<const float2*>(&g_bias[ocol0 + nt * 8]);
        #pragma unroll
        for (int mt = 0; mt < 2; mt++) {
            int r0 = orow0 + mt * 16;
            float* p0 = out + (size_t)r0 * N_TOTAL + ocol0 + nt * 8;
            float* p1 = out + (size_t)(r0 + 8) * N_TOTAL + ocol0 + nt * 8;
            *reinterpret_cast<float2*>(p0) = make_float2(acc[mt][nt][0] + bv.x, acc[mt][nt][1] + bv.y);
            *reinterpret_cast<float2*>(p1) = make_float2(acc[mt][nt][2] + bv.x, acc[mt][nt][3] + bv.y);
        }
    }
}

// ---------------- host launcher ----------------
extern "C" void kernel_launch(void* const* d_in, const int* in_sizes, int n_in,
                              void* d_out, int out_size) {
    const float* x      = (const float*)d_in[0];
    const int*   wp     = (const int*)d_in[1];
    const void*  scales = d_in[2];
    const void*  bias   = d_in[3];
    float*       out    = (float*)d_out;

    void* wptr = nullptr; cudaGetSymbolAddress(&wptr, g_W);
    void* xptr = nullptr; cudaGetSymbolAddress(&xptr, g_X);

    detect_kernel<<<1, 1>>>((const uint32_t*)scales);
    dequant_kernel<<<(NUM_GROUPS * 16 + 255) / 256, 256>>>(wp, scales, (__half*)wptr);
    bias_cvt_kernel<<<(N_TOTAL + 255) / 256, 256>>>(bias);
    cvt_kernel<<<((M_TOTAL * K_TOTAL) / 4 + 255) / 256, 256>>>((const float4*)x, (__half2*)xptr);

    cudaFuncSetAttribute(gemm_kernel, cudaFuncAttributeMaxDynamicSharedMemorySize, SMEM_TOTAL);
    gemm_kernel<<<MT * NT, 256, SMEM_TOTAL>>>((const __half*)xptr, (const __half*)wptr, out);
}